// round 11
// baseline (speedup 1.0000x reference)
#include <cuda_runtime.h>
#include <cuda_bf16.h>
#include <math.h>
#include <stdint.h>

#define NP    16384
#define DIM   24
#define ESIG  65536
#define ERND  32768
#define KK    50          // reference keeps K+1 (self + K nearest)
#define CANDMAX 64
#define D2_SLACK 8.0f     // bf16 threshold (true cutoff 1.0; error bound ~1.2)

#define MT     128        // tile rows
#define NTILES (NP/MT)    // 128
#define CHUNK  8          // tj tiles per scan CTA
#define NCHUNK 1088       // sum over ti of ceil((128-ti)/8)

#define PREP_BLKS  (NP*2/256)            // 128
#define SIG_BLKS   (ESIG/(256*4))        // 64
#define RND_BLKS   (ERND/(256*4))        // 32
#define EDGE_END   (PREP_BLKS + SIG_BLKS + RND_BLKS)   // 224
#define MEGA_BLKS  (EDGE_END + NCHUNK)                 // 1312

// ---------------- device state (static zero-init; finalize resets) ----------------
__device__ double g_acc[3];
__device__ int    g_done;
__device__ int    g_prep_done;
__device__ float  g_sq[NP];
__device__ float  g_sqh[NP];
__device__ int    g_pid[NP];
__device__ int    g_ccnt[NP];
__device__ int    g_cidx[NP][CANDMAX];
__device__ uint32_t g_P[NP][8];   // dims 0-15, pair layout [w0,w4,w1,w5,w2,w6,w3,w7]
__device__ uint32_t g_Q[NP][4];   // dims 16-23

// ---------------- helpers ----------------
__device__ __forceinline__ long long ldidx(const void* p, long long i, int is64) {
    if (is64) return ((const long long*)p)[i];
    return (long long)((const int*)p)[i];
}
__device__ __forceinline__ int detect64(const void* p, long long lim) {
    const long long* q = (const long long*)p;
    for (int i = 0; i < 32; i++) {
        long long v = q[i];
        if (v < 0 || v >= lim) return 0;
    }
    return 1;
}
template <int BS>
__device__ __forceinline__ void block_accum(double v, double* target) {
    __shared__ double s[BS];
    int t = threadIdx.x;
    s[t] = v;
    __syncthreads();
    for (int o = BS / 2; o > 0; o >>= 1) {
        if (t < o) s[t] += s[t + o];
        __syncthreads();
    }
    if (t == 0 && s[0] != 0.0) atomicAdd(target, s[0]);
}
__device__ __forceinline__ uint32_t smem_u32(const void* p) {
    uint32_t a;
    asm("{ .reg .u64 t; cvta.to.shared.u64 t, %1; cvt.u32.u64 %0, t; }" : "=r"(a) : "l"(p));
    return a;
}
__device__ __forceinline__ void cpa16(uint32_t s, const void* g) {
    asm volatile("cp.async.cg.shared.global [%0], [%1], 16;" :: "r"(s), "l"(g));
}
#define CPA_COMMIT() asm volatile("cp.async.commit_group;" ::: "memory")
#define CPA_WAIT0()  asm volatile("cp.async.wait_group 0;" ::: "memory")

__device__ __forceinline__ void mma16816(float* d, const uint32_t* a, uint32_t b0, uint32_t b1) {
    asm volatile(
        "mma.sync.aligned.m16n8k16.row.col.f32.bf16.bf16.f32 "
        "{%0,%1,%2,%3}, {%4,%5,%6,%7}, {%8,%9}, {%0,%1,%2,%3};"
        : "+f"(d[0]), "+f"(d[1]), "+f"(d[2]), "+f"(d[3])
        : "r"(a[0]), "r"(a[1]), "r"(a[2]), "r"(a[3]), "r"(b0), "r"(b1));
}
__device__ __forceinline__ void mma1688(float* d, uint32_t a0, uint32_t a1, uint32_t b0) {
    asm volatile(
        "mma.sync.aligned.m16n8k8.row.col.f32.bf16.bf16.f32 "
        "{%0,%1,%2,%3}, {%4,%5}, {%6}, {%0,%1,%2,%3};"
        : "+f"(d[0]), "+f"(d[1]), "+f"(d[2]), "+f"(d[3])
        : "r"(a0), "r"(a1), "r"(b0));
}

__device__ __forceinline__ float edge_d2(const float* __restrict__ emb,
                                         long long a, long long b) {
    const float4* pa = (const float4*)(emb + a * DIM);
    const float4* pb = (const float4*)(emb + b * DIM);
    float s = 0.f;
    #pragma unroll
    for (int q = 0; q < DIM / 4; q++) {
        float4 x = pa[q], y = pb[q];
        float d0 = x.x - y.x, d1 = x.y - y.y, d2 = x.z - y.z, d3 = x.w - y.w;
        s = fmaf(d0, d0, s); s = fmaf(d1, d1, s);
        s = fmaf(d2, d2, s); s = fmaf(d3, d3, s);
    }
    return s;
}

__device__ __forceinline__ uint32_t bf2w(float lo, float hi) {
    __nv_bfloat162 p = __floats2bfloat162_rn(lo, hi);
    return *(uint32_t*)&p;
}

// ---------------- mega kernel: prep | edges | chunked triangular scan ----------------
__global__ void __launch_bounds__(256) k_mega(const float* __restrict__ emb,
                                              const void* __restrict__ sig,
                                              const void* __restrict__ rnd,
                                              const void* __restrict__ pid) {
    int bx = blockIdx.x;
    int t  = threadIdx.x;

    if (bx < PREP_BLKS) {
        // ---- prep: 2 threads per point ----
        __shared__ int s_is64;
        if (t == 0) s_is64 = detect64(pid, 1LL << 31);
        __syncthreads();
        int pt = bx * 128 + (t >> 1);
        int h  = t & 1;
        const float4* src = (const float4*)(emb + (long long)pt * DIM);
        float s = 0.f;
        if (h == 0) {
            float4 v[4];
            #pragma unroll
            for (int q = 0; q < 4; q++) v[q] = src[q];
            float f[16];
            #pragma unroll
            for (int q = 0; q < 4; q++) {
                f[4 * q] = v[q].x; f[4 * q + 1] = v[q].y;
                f[4 * q + 2] = v[q].z; f[4 * q + 3] = v[q].w;
            }
            #pragma unroll
            for (int k = 0; k < 16; k++) s = fmaf(f[k], f[k], s);
            uint32_t w[8];
            #pragma unroll
            for (int j = 0; j < 8; j++) w[j] = bf2w(f[2 * j], f[2 * j + 1]);
            uint4* dst = (uint4*)g_P[pt];
            dst[0] = make_uint4(w[0], w[4], w[1], w[5]);
            dst[1] = make_uint4(w[2], w[6], w[3], w[7]);
        } else {
            float4 v0 = src[4], v1 = src[5];
            s = fmaf(v0.x, v0.x, s); s = fmaf(v0.y, v0.y, s);
            s = fmaf(v0.z, v0.z, s); s = fmaf(v0.w, v0.w, s);
            s = fmaf(v1.x, v1.x, s); s = fmaf(v1.y, v1.y, s);
            s = fmaf(v1.z, v1.z, s); s = fmaf(v1.w, v1.w, s);
            *(uint4*)g_Q[pt] = make_uint4(bf2w(v0.x, v0.y), bf2w(v0.z, v0.w),
                                          bf2w(v1.x, v1.y), bf2w(v1.z, v1.w));
        }
        float tot = s + __shfl_xor_sync(0xffffffff, s, 1);
        if (h == 1) {
            g_sq[pt]   = tot;
            g_sqh[pt]  = 0.5f * tot;
            g_pid[pt]  = (int)ldidx(pid, pt, s_is64);
            g_ccnt[pt] = 0;
        }
        __syncthreads();
        __threadfence();
        if (t == 0) atomicAdd(&g_prep_done, 1);
        return;
    }

    if (bx < EDGE_END) {
        // ---- edges (prep-independent: read raw inputs) ----
        __shared__ int s_is64e, s_is64p;
        int eb = bx - PREP_BLKS;
        if (eb < SIG_BLKS) {
            if (t == 0) s_is64e = detect64(sig, (long long)NP);
            __syncthreads();
            int base = eb * 256 * 4 + t * 4;
            int is64 = s_is64e;
            float s = 0.f;
            #pragma unroll
            for (int e = 0; e < 4; e++) {
                long long a = ldidx(sig, base + e, is64);
                long long b = ldidx(sig, (long long)ESIG + base + e, is64);
                s += edge_d2(emb, a, b) + 1e-12f;
            }
            block_accum<256>((double)s, &g_acc[0]);
        } else {
            if (t == 0) {
                s_is64e = detect64(rnd, (long long)NP);
                s_is64p = detect64(pid, 1LL << 31);
            }
            __syncthreads();
            int base = (eb - SIG_BLKS) * 256 * 4 + t * 4;
            int is64 = s_is64e, is64p = s_is64p;
            float s = 0.f;
            #pragma unroll
            for (int e = 0; e < 4; e++) {
                long long a = ldidx(rnd, base + e, is64);
                long long b = ldidx(rnd, (long long)ERND + base + e, is64);
                if (ldidx(pid, a, is64p) != ldidx(pid, b, is64p)) {
                    float dd = sqrtf(edge_d2(emb, a, b) + 1e-12f);
                    if (dd < 1.0f) {
                        float h = 1.0f - dd;
                        s += h * h;
                    }
                }
            }
            block_accum<256>((double)s, &g_acc[2]);
        }
        return;
    }

    // ---- chunked symmetric scan: one CTA = row-tile ti vs up to 8 tj tiles ----
    __shared__ __align__(16) uint32_t sAP[MT * 8];       // 4 KB
    __shared__ __align__(16) uint32_t sAQ[MT * 4];       // 2 KB
    __shared__ __align__(16) uint32_t sBP[2][MT * 8];    // 8 KB
    __shared__ __align__(16) uint32_t sBQ[2][MT * 4];    // 4 KB
    __shared__ __align__(16) float    sbh[2][MT];        // 1 KB

    int c = bx - EDGE_END;
    int ti = 0, rem = c;
    while (true) {
        int ch = (NTILES - ti + CHUNK - 1) >> 3;
        if (rem < ch) break;
        rem -= ch; ti++;
    }
    int tj0 = ti + (rem << 3);
    int tjn = NTILES - tj0; if (tjn > CHUNK) tjn = CHUNK;

    // wait for prep (prep blocks are bids 0..127 -> wave 1; no deadlock)
    if (t == 0) {
        while (*((volatile int*)&g_prep_done) < PREP_BLKS) __nanosleep(64);
    }
    __syncthreads();
    __threadfence();

    int wid  = t >> 5;
    int lane = t & 31;
    int g    = lane >> 2;
    int tig  = lane & 3;

    // stage A + first B tile
    {
        int row = t >> 1, h = t & 1;
        cpa16(smem_u32(&sAP[row * 8 + h * 4]), &g_P[ti * MT + row][h * 4]);
        cpa16(smem_u32(&sBP[0][row * 8 + h * 4]), &g_P[tj0 * MT + row][h * 4]);
        if (t < MT) cpa16(smem_u32(&sAQ[t * 4]), &g_Q[ti * MT + t][0]);
        else if (t < 2 * MT) cpa16(smem_u32(&sBQ[0][(t - MT) * 4]), &g_Q[tj0 * MT + (t - MT)][0]);
        if (t < MT / 4) cpa16(smem_u32(&sbh[0][t * 4]), &g_sqh[tj0 * MT + t * 4]);
        CPA_COMMIT();
        CPA_WAIT0();
    }
    __syncthreads();

    // A fragments (loaded once per chunk)
    int sbase = wid * 16;
    uint32_t a16[4], a8_0, a8_1;
    {
        int r0 = sbase + g, r1 = sbase + g + 8;
        uint2 p;
        p = *(const uint2*)&sAP[r0 * 8 + 2 * tig]; a16[0] = p.x; a16[2] = p.y;
        p = *(const uint2*)&sAP[r1 * 8 + 2 * tig]; a16[1] = p.x; a16[3] = p.y;
        a8_0 = sAQ[r0 * 4 + tig];
        a8_1 = sAQ[r1 * 4 + tig];
    }
    int rowg0 = ti * MT + sbase + g;
    int rowg1 = rowg0 + 8;
    float thr0 = 0.5f * (g_sq[rowg0] - D2_SLACK);
    float thr1 = 0.5f * (g_sq[rowg1] - D2_SLACK);
    float thrmin = fminf(thr0, thr1);

    for (int jj = 0; jj < tjn; jj++) {
        int tj  = tj0 + jj;
        int buf = jj & 1;

        if (jj + 1 < tjn) {       // prefetch next B tile
            int tn = tj + 1, nb2 = buf ^ 1;
            int row = t >> 1, h = t & 1;
            cpa16(smem_u32(&sBP[nb2][row * 8 + h * 4]), &g_P[tn * MT + row][h * 4]);
            if (t < MT) cpa16(smem_u32(&sBQ[nb2][t * 4]), &g_Q[tn * MT + t][0]);
            if (t < MT / 4) cpa16(smem_u32(&sbh[nb2][t * 4]), &g_sqh[tn * MT + t * 4]);
            CPA_COMMIT();
        }

        bool offdiag = (tj != ti);
        int cbase = tj * MT;
        const uint32_t* BP = sBP[buf];
        const uint32_t* BQ = sBQ[buf];
        const float*    SH = sbh[buf];

        #pragma unroll 4
        for (int nb = 0; nb < MT / 8; nb++) {
            int cb = nb * 8;
            uint2 bp = *(const uint2*)&BP[(cb + g) * 8 + 2 * tig];
            uint32_t bq = BQ[(cb + g) * 4 + tig];

            float d[4] = {0.f, 0.f, 0.f, 0.f};
            mma16816(d, a16, bp.x, bp.y);
            mma1688(d, a8_0, a8_1, bq);

            int c0 = cb + tig * 2;
            float2 sb2 = *(const float2*)&SH[c0];
            float dmax = fmaxf(fmaxf(d[0], d[1]), fmaxf(d[2], d[3]));
            if (dmax > thrmin + fminf(sb2.x, sb2.y)) {       // rare
                if (d[0] > thr0 + sb2.x) {
                    int jg = cbase + c0;
                    int p = atomicAdd(&g_ccnt[rowg0], 1);
                    if (p < CANDMAX) g_cidx[rowg0][p] = jg;
                    if (offdiag) {
                        int q = atomicAdd(&g_ccnt[jg], 1);
                        if (q < CANDMAX) g_cidx[jg][q] = rowg0;
                    }
                }
                if (d[1] > thr0 + sb2.y) {
                    int jg = cbase + c0 + 1;
                    int p = atomicAdd(&g_ccnt[rowg0], 1);
                    if (p < CANDMAX) g_cidx[rowg0][p] = jg;
                    if (offdiag) {
                        int q = atomicAdd(&g_ccnt[jg], 1);
                        if (q < CANDMAX) g_cidx[jg][q] = rowg0;
                    }
                }
                if (d[2] > thr1 + sb2.x) {
                    int jg = cbase + c0;
                    int p = atomicAdd(&g_ccnt[rowg1], 1);
                    if (p < CANDMAX) g_cidx[rowg1][p] = jg;
                    if (offdiag) {
                        int q = atomicAdd(&g_ccnt[jg], 1);
                        if (q < CANDMAX) g_cidx[jg][q] = rowg1;
                    }
                }
                if (d[3] > thr1 + sb2.y) {
                    int jg = cbase + c0 + 1;
                    int p = atomicAdd(&g_ccnt[rowg1], 1);
                    if (p < CANDMAX) g_cidx[rowg1][p] = jg;
                    if (offdiag) {
                        int q = atomicAdd(&g_ccnt[jg], 1);
                        if (q < CANDMAX) g_cidx[jg][q] = rowg1;
                    }
                }
            }
        }
        CPA_WAIT0();
        __syncthreads();
    }
}

// ---------------- finalize: fast-path + exact recompute + hinge + finish + reset ----------------
__global__ void k_finalize(const float* __restrict__ emb, float* out) {
    int row = blockIdx.x * blockDim.x + threadIdx.x;
    double local = 0.0;
    int nc = (row < NP) ? g_ccnt[row] : 0;
    if (nc > CANDMAX) nc = CANDMAX;
    if (nc > 1) {      // nc==1 => only self => contributes 0
        float cd2[CANDMAX];
        int   cidx[CANDMAX];
        float sqr = g_sq[row];
        const float4* pr = (const float4*)(emb + (long long)row * DIM);
        float4 r4[DIM / 4];
        #pragma unroll
        for (int q = 0; q < DIM / 4; q++) r4[q] = pr[q];
        for (int qq = 0; qq < nc; qq++) {
            int j = g_cidx[row][qq];
            const float4* pc = (const float4*)(emb + (long long)j * DIM);
            float dot = 0.f;
            #pragma unroll
            for (int q = 0; q < DIM / 4; q++) {
                float4 y = pc[q];
                dot = fmaf(r4[q].x, y.x, dot); dot = fmaf(r4[q].y, y.y, dot);
                dot = fmaf(r4[q].z, y.z, dot); dot = fmaf(r4[q].w, y.w, dot);
            }
            cd2[qq]  = sqr + g_sq[j] - 2.0f * dot;   // exact fp32
            cidx[qq] = j;
        }
        for (int i = 1; i < nc; i++) {               // ascending (d2, idx)
            float dv = cd2[i]; int iv = cidx[i];
            int j = i - 1;
            while (j >= 0 && (cd2[j] > dv || (cd2[j] == dv && cidx[j] > iv))) {
                cd2[j + 1] = cd2[j]; cidx[j + 1] = cidx[j]; j--;
            }
            cd2[j + 1] = dv; cidx[j + 1] = iv;
        }
        int mypid = g_pid[row];
        int lim = nc < (KK + 1) ? nc : (KK + 1);
        for (int q = 0; q < lim; q++) {
            int j = cidx[q];
            if (j != row && g_pid[j] != mypid) {
                float d = sqrtf(fmaxf(cd2[q], 0.0f) + 1e-12f);
                if (d < 1.0f) {
                    float h = 1.0f - d;
                    local += (double)(h * h);
                }
            }
        }
    }
    block_accum<128>(local, &g_acc[1]);

    if (threadIdx.x == 0) {
        __threadfence();
        int done = atomicAdd(&g_done, 1);
        if (done == (int)gridDim.x - 1) {
            out[0] = (float)(g_acc[0] / (double)ESIG +
                             g_acc[1] / (double)NP +
                             g_acc[2] / (double)ERND);
            // reset for next graph replay
            g_acc[0] = 0.0; g_acc[1] = 0.0; g_acc[2] = 0.0;
            g_done = 0;
            g_prep_done = 0;
        }
    }
}

// ---------------- launch ----------------
extern "C" void kernel_launch(void* const* d_in, const int* in_sizes, int n_in,
                              void* d_out, int out_size) {
    const float* emb = (const float*)d_in[0];
    const void*  sig = d_in[1];
    const void*  rnd = d_in[2];
    const void*  pid = d_in[3];
    float* out = (float*)d_out;

    k_mega<<<MEGA_BLKS, 256>>>(emb, sig, rnd, pid);
    k_finalize<<<NP / 128, 128>>>(emb, out);
}

// round 13
// speedup vs baseline: 1.0581x; 1.0581x over previous
#include <cuda_runtime.h>
#include <cuda_bf16.h>
#include <math.h>
#include <stdint.h>

#define NP    16384
#define DIM   24
#define ESIG  65536
#define ERND  32768
#define KK    50          // reference keeps K+1 (self + K nearest)
#define CANDMAX 64
#define D2_SLACK 8.0f     // bf16 threshold (true cutoff 1.0; error bound ~1.2)

#define MT     128        // tile rows
#define NTILES (NP/MT)    // 128
#define CHUNK  8          // tj tiles per scan CTA
#define NCHUNK 1088       // sum over ti of ceil((128-ti)/8)

#define FIN_BLKS   (NP/256)              // 64
#define SIG_BLKS   (ESIG/(256*4))        // 64
#define RND_BLKS   (ERND/(256*4))        // 32
#define FINAL_BLKS (FIN_BLKS + SIG_BLKS + RND_BLKS)   // 160

// ---------------- device state (static zero-init; final kernel resets) ----------------
__device__ double g_acc[3];
__device__ int    g_done;
__device__ float  g_sq[NP];
__device__ float  g_sqh[NP];
__device__ int    g_pid[NP];
__device__ int    g_ccnt[NP];
__device__ int    g_cidx[NP][CANDMAX];
__device__ uint32_t g_P[NP][8];   // dims 0-15, pair layout [w0,w4,w1,w5,w2,w6,w3,w7]
__device__ uint32_t g_Q[NP][4];   // dims 16-23

// ---------------- helpers ----------------
__device__ __forceinline__ long long ldidx(const void* p, long long i, int is64) {
    if (is64) return ((const long long*)p)[i];
    return (long long)((const int*)p)[i];
}
__device__ __forceinline__ int detect64(const void* p, long long lim) {
    const long long* q = (const long long*)p;
    for (int i = 0; i < 32; i++) {
        long long v = q[i];
        if (v < 0 || v >= lim) return 0;
    }
    return 1;
}
template <int BS>
__device__ __forceinline__ void block_accum(double v, double* target) {
    __shared__ double s[BS];
    int t = threadIdx.x;
    s[t] = v;
    __syncthreads();
    for (int o = BS / 2; o > 0; o >>= 1) {
        if (t < o) s[t] += s[t + o];
        __syncthreads();
    }
    if (t == 0 && s[0] != 0.0) atomicAdd(target, s[0]);
}
__device__ __forceinline__ uint32_t smem_u32(const void* p) {
    uint32_t a;
    asm("{ .reg .u64 t; cvta.to.shared.u64 t, %1; cvt.u32.u64 %0, t; }" : "=r"(a) : "l"(p));
    return a;
}
__device__ __forceinline__ void cpa16(uint32_t s, const void* g) {
    asm volatile("cp.async.cg.shared.global [%0], [%1], 16;" :: "r"(s), "l"(g));
}
#define CPA_COMMIT() asm volatile("cp.async.commit_group;" ::: "memory")
#define CPA_WAIT0()  asm volatile("cp.async.wait_group 0;" ::: "memory")

__device__ __forceinline__ void mma16816(float* d, const uint32_t* a, uint32_t b0, uint32_t b1) {
    asm volatile(
        "mma.sync.aligned.m16n8k16.row.col.f32.bf16.bf16.f32 "
        "{%0,%1,%2,%3}, {%4,%5,%6,%7}, {%8,%9}, {%0,%1,%2,%3};"
        : "+f"(d[0]), "+f"(d[1]), "+f"(d[2]), "+f"(d[3])
        : "r"(a[0]), "r"(a[1]), "r"(a[2]), "r"(a[3]), "r"(b0), "r"(b1));
}
__device__ __forceinline__ void mma1688(float* d, uint32_t a0, uint32_t a1, uint32_t b0) {
    asm volatile(
        "mma.sync.aligned.m16n8k8.row.col.f32.bf16.bf16.f32 "
        "{%0,%1,%2,%3}, {%4,%5}, {%6}, {%0,%1,%2,%3};"
        : "+f"(d[0]), "+f"(d[1]), "+f"(d[2]), "+f"(d[3])
        : "r"(a0), "r"(a1), "r"(b0));
}

__device__ __forceinline__ float edge_d2(const float* __restrict__ emb,
                                         long long a, long long b) {
    const float4* pa = (const float4*)(emb + a * DIM);
    const float4* pb = (const float4*)(emb + b * DIM);
    float s = 0.f;
    #pragma unroll
    for (int q = 0; q < DIM / 4; q++) {
        float4 x = pa[q], y = pb[q];
        float d0 = x.x - y.x, d1 = x.y - y.y, d2 = x.z - y.z, d3 = x.w - y.w;
        s = fmaf(d0, d0, s); s = fmaf(d1, d1, s);
        s = fmaf(d2, d2, s); s = fmaf(d3, d3, s);
    }
    return s;
}

__device__ __forceinline__ uint32_t bf2w(float lo, float hi) {
    __nv_bfloat162 p = __floats2bfloat162_rn(lo, hi);
    return *(uint32_t*)&p;
}

// ---------------- prep: 2 threads per point ----------------
__global__ void __launch_bounds__(256) k_prep(const float* __restrict__ emb,
                                              const void* __restrict__ pid) {
    __shared__ int s_is64;
    if (threadIdx.x == 0) s_is64 = detect64(pid, 1LL << 31);
    __syncthreads();
    int t  = threadIdx.x;
    int pt = blockIdx.x * 128 + (t >> 1);
    int h  = t & 1;
    const float4* src = (const float4*)(emb + (long long)pt * DIM);
    float s = 0.f;
    if (h == 0) {
        float4 v[4];
        #pragma unroll
        for (int q = 0; q < 4; q++) v[q] = src[q];
        float f[16];
        #pragma unroll
        for (int q = 0; q < 4; q++) {
            f[4 * q] = v[q].x; f[4 * q + 1] = v[q].y;
            f[4 * q + 2] = v[q].z; f[4 * q + 3] = v[q].w;
        }
        #pragma unroll
        for (int k = 0; k < 16; k++) s = fmaf(f[k], f[k], s);
        uint32_t w[8];
        #pragma unroll
        for (int j = 0; j < 8; j++) w[j] = bf2w(f[2 * j], f[2 * j + 1]);
        uint4* dst = (uint4*)g_P[pt];
        dst[0] = make_uint4(w[0], w[4], w[1], w[5]);
        dst[1] = make_uint4(w[2], w[6], w[3], w[7]);
    } else {
        float4 v0 = src[4], v1 = src[5];
        s = fmaf(v0.x, v0.x, s); s = fmaf(v0.y, v0.y, s);
        s = fmaf(v0.z, v0.z, s); s = fmaf(v0.w, v0.w, s);
        s = fmaf(v1.x, v1.x, s); s = fmaf(v1.y, v1.y, s);
        s = fmaf(v1.z, v1.z, s); s = fmaf(v1.w, v1.w, s);
        *(uint4*)g_Q[pt] = make_uint4(bf2w(v0.x, v0.y), bf2w(v0.z, v0.w),
                                      bf2w(v1.x, v1.y), bf2w(v1.z, v1.w));
    }
    float tot = s + __shfl_xor_sync(0xffffffff, s, 1);
    if (h == 1) {
        g_sq[pt]   = tot;
        g_sqh[pt]  = 0.5f * tot;
        g_pid[pt]  = (int)ldidx(pid, pt, s_is64);
        g_ccnt[pt] = 0;
    }
}

// ---------------- pure chunked symmetric scan ----------------
__global__ void __launch_bounds__(256) k_scan(void) {
    __shared__ __align__(16) uint32_t sAP[MT * 8];       // 4 KB
    __shared__ __align__(16) uint32_t sAQ[MT * 4];       // 2 KB
    __shared__ __align__(16) uint32_t sBP[2][MT * 8];    // 8 KB
    __shared__ __align__(16) uint32_t sBQ[2][MT * 4];    // 4 KB
    __shared__ __align__(16) float    sbh[2][MT];        // 1 KB

    int t = threadIdx.x;
    int c = blockIdx.x;
    int ti = 0, rem = c;
    while (true) {
        int ch = (NTILES - ti + CHUNK - 1) >> 3;
        if (rem < ch) break;
        rem -= ch; ti++;
    }
    int tj0 = ti + (rem << 3);
    int tjn = NTILES - tj0; if (tjn > CHUNK) tjn = CHUNK;

    int wid  = t >> 5;
    int lane = t & 31;
    int g    = lane >> 2;
    int tig  = lane & 3;

    // stage A + first B tile
    {
        int row = t >> 1, h = t & 1;
        cpa16(smem_u32(&sAP[row * 8 + h * 4]), &g_P[ti * MT + row][h * 4]);
        cpa16(smem_u32(&sBP[0][row * 8 + h * 4]), &g_P[tj0 * MT + row][h * 4]);
        if (t < MT) cpa16(smem_u32(&sAQ[t * 4]), &g_Q[ti * MT + t][0]);
        else cpa16(smem_u32(&sBQ[0][(t - MT) * 4]), &g_Q[tj0 * MT + (t - MT)][0]);
        if (t < MT / 4) cpa16(smem_u32(&sbh[0][t * 4]), &g_sqh[tj0 * MT + t * 4]);
        CPA_COMMIT();
        CPA_WAIT0();
    }
    __syncthreads();

    // A fragments (loaded once per chunk)
    int sbase = wid * 16;
    uint32_t a16[4], a8_0, a8_1;
    {
        int r0 = sbase + g, r1 = sbase + g + 8;
        uint2 p;
        p = *(const uint2*)&sAP[r0 * 8 + 2 * tig]; a16[0] = p.x; a16[2] = p.y;
        p = *(const uint2*)&sAP[r1 * 8 + 2 * tig]; a16[1] = p.x; a16[3] = p.y;
        a8_0 = sAQ[r0 * 4 + tig];
        a8_1 = sAQ[r1 * 4 + tig];
    }
    int rowg0 = ti * MT + sbase + g;
    int rowg1 = rowg0 + 8;
    float thr0 = 0.5f * (g_sq[rowg0] - D2_SLACK);
    float thr1 = 0.5f * (g_sq[rowg1] - D2_SLACK);
    float thrmin = fminf(thr0, thr1);

    for (int jj = 0; jj < tjn; jj++) {
        int tj  = tj0 + jj;
        int buf = jj & 1;

        if (jj + 1 < tjn) {       // prefetch next B tile
            int tn = tj + 1, nb2 = buf ^ 1;
            int row = t >> 1, h = t & 1;
            cpa16(smem_u32(&sBP[nb2][row * 8 + h * 4]), &g_P[tn * MT + row][h * 4]);
            if (t < MT) cpa16(smem_u32(&sBQ[nb2][t * 4]), &g_Q[tn * MT + t][0]);
            if (t < MT / 4) cpa16(smem_u32(&sbh[nb2][t * 4]), &g_sqh[tn * MT + t * 4]);
            CPA_COMMIT();
        }

        bool offdiag = (tj != ti);
        int cbase = tj * MT;
        const uint32_t* BP = sBP[buf];
        const uint32_t* BQ = sBQ[buf];
        const float*    SH = sbh[buf];

        #pragma unroll 4
        for (int nb = 0; nb < MT / 8; nb++) {
            int cb = nb * 8;
            uint2 bp = *(const uint2*)&BP[(cb + g) * 8 + 2 * tig];
            uint32_t bq = BQ[(cb + g) * 4 + tig];

            float d[4] = {0.f, 0.f, 0.f, 0.f};
            mma16816(d, a16, bp.x, bp.y);
            mma1688(d, a8_0, a8_1, bq);

            int c0 = cb + tig * 2;
            float2 sb2 = *(const float2*)&SH[c0];
            float dmax = fmaxf(fmaxf(d[0], d[1]), fmaxf(d[2], d[3]));
            if (dmax > thrmin + fminf(sb2.x, sb2.y)) {       // rare
                if (d[0] > thr0 + sb2.x) {
                    int jg = cbase + c0;
                    int p = atomicAdd(&g_ccnt[rowg0], 1);
                    if (p < CANDMAX) g_cidx[rowg0][p] = jg;
                    if (offdiag) {
                        int q = atomicAdd(&g_ccnt[jg], 1);
                        if (q < CANDMAX) g_cidx[jg][q] = rowg0;
                    }
                }
                if (d[1] > thr0 + sb2.y) {
                    int jg = cbase + c0 + 1;
                    int p = atomicAdd(&g_ccnt[rowg0], 1);
                    if (p < CANDMAX) g_cidx[rowg0][p] = jg;
                    if (offdiag) {
                        int q = atomicAdd(&g_ccnt[jg], 1);
                        if (q < CANDMAX) g_cidx[jg][q] = rowg0;
                    }
                }
                if (d[2] > thr1 + sb2.x) {
                    int jg = cbase + c0;
                    int p = atomicAdd(&g_ccnt[rowg1], 1);
                    if (p < CANDMAX) g_cidx[rowg1][p] = jg;
                    if (offdiag) {
                        int q = atomicAdd(&g_ccnt[jg], 1);
                        if (q < CANDMAX) g_cidx[jg][q] = rowg1;
                    }
                }
                if (d[3] > thr1 + sb2.y) {
                    int jg = cbase + c0 + 1;
                    int p = atomicAdd(&g_ccnt[rowg1], 1);
                    if (p < CANDMAX) g_cidx[rowg1][p] = jg;
                    if (offdiag) {
                        int q = atomicAdd(&g_ccnt[jg], 1);
                        if (q < CANDMAX) g_cidx[jg][q] = rowg1;
                    }
                }
            }
        }
        CPA_WAIT0();
        __syncthreads();
    }
}

// ---------------- final: finalize rows | signal | random, then finish+reset ----------------
__global__ void __launch_bounds__(256) k_final(const float* __restrict__ emb,
                                               const void* __restrict__ sig,
                                               const void* __restrict__ rnd,
                                               float* out) {
    int bx = blockIdx.x;
    int t  = threadIdx.x;

    if (bx < FIN_BLKS) {
        // ---- finalize rows ----
        int row = bx * 256 + t;
        double local = 0.0;
        int nc = g_ccnt[row];
        if (nc > CANDMAX) nc = CANDMAX;
        if (nc > 1) {      // nc==1 => only self => contributes 0
            float cd2[CANDMAX];
            int   cidx[CANDMAX];
            float sqr = g_sq[row];
            const float4* pr = (const float4*)(emb + (long long)row * DIM);
            float4 r4[DIM / 4];
            #pragma unroll
            for (int q = 0; q < DIM / 4; q++) r4[q] = pr[q];
            for (int qq = 0; qq < nc; qq++) {
                int j = g_cidx[row][qq];
                const float4* pc = (const float4*)(emb + (long long)j * DIM);
                float dot = 0.f;
                #pragma unroll
                for (int q = 0; q < DIM / 4; q++) {
                    float4 y = pc[q];
                    dot = fmaf(r4[q].x, y.x, dot); dot = fmaf(r4[q].y, y.y, dot);
                    dot = fmaf(r4[q].z, y.z, dot); dot = fmaf(r4[q].w, y.w, dot);
                }
                cd2[qq]  = sqr + g_sq[j] - 2.0f * dot;   // exact fp32
                cidx[qq] = j;
            }
            for (int i = 1; i < nc; i++) {               // ascending (d2, idx)
                float dv = cd2[i]; int iv = cidx[i];
                int j = i - 1;
                while (j >= 0 && (cd2[j] > dv || (cd2[j] == dv && cidx[j] > iv))) {
                    cd2[j + 1] = cd2[j]; cidx[j + 1] = cidx[j]; j--;
                }
                cd2[j + 1] = dv; cidx[j + 1] = iv;
            }
            int mypid = g_pid[row];
            int lim = nc < (KK + 1) ? nc : (KK + 1);
            for (int q = 0; q < lim; q++) {
                int j = cidx[q];
                if (j != row && g_pid[j] != mypid) {
                    float d = sqrtf(fmaxf(cd2[q], 0.0f) + 1e-12f);
                    if (d < 1.0f) {
                        float h = 1.0f - d;
                        local += (double)(h * h);
                    }
                }
            }
        }
        block_accum<256>(local, &g_acc[1]);
    } else if (bx < FIN_BLKS + SIG_BLKS) {
        // ---- signal ----
        __shared__ int s_is64;
        if (t == 0) s_is64 = detect64(sig, (long long)NP);
        __syncthreads();
        int base = (bx - FIN_BLKS) * 256 * 4 + t * 4;
        int is64 = s_is64;
        float s = 0.f;
        #pragma unroll
        for (int e = 0; e < 4; e++) {
            long long a = ldidx(sig, base + e, is64);
            long long b = ldidx(sig, (long long)ESIG + base + e, is64);
            s += edge_d2(emb, a, b) + 1e-12f;
        }
        block_accum<256>((double)s, &g_acc[0]);
    } else {
        // ---- random ----
        __shared__ int s_is64;
        if (t == 0) s_is64 = detect64(rnd, (long long)NP);
        __syncthreads();
        int base = (bx - FIN_BLKS - SIG_BLKS) * 256 * 4 + t * 4;
        int is64 = s_is64;
        float s = 0.f;
        #pragma unroll
        for (int e = 0; e < 4; e++) {
            long long a = ldidx(rnd, base + e, is64);
            long long b = ldidx(rnd, (long long)ERND + base + e, is64);
            if (g_pid[a] != g_pid[b]) {
                float dd = sqrtf(edge_d2(emb, a, b) + 1e-12f);
                if (dd < 1.0f) {
                    float h = 1.0f - dd;
                    s += h * h;
                }
            }
        }
        block_accum<256>((double)s, &g_acc[2]);
    }

    if (t == 0) {
        __threadfence();
        int done = atomicAdd(&g_done, 1);
        if (done == FINAL_BLKS - 1) {
            out[0] = (float)(g_acc[0] / (double)ESIG +
                             g_acc[1] / (double)NP +
                             g_acc[2] / (double)ERND);
            // reset for next graph replay
            g_acc[0] = 0.0; g_acc[1] = 0.0; g_acc[2] = 0.0;
            g_done = 0;
        }
    }
}

// ---------------- launch ----------------
extern "C" void kernel_launch(void* const* d_in, const int* in_sizes, int n_in,
                              void* d_out, int out_size) {
    const float* emb = (const float*)d_in[0];
    const void*  sig = d_in[1];
    const void*  rnd = d_in[2];
    const void*  pid = d_in[3];
    float* out = (float*)d_out;

    k_prep<<<NP * 2 / 256, 256>>>(emb, pid);
    k_scan<<<NCHUNK, 256>>>();
    k_final<<<FINAL_BLKS, 256>>>(emb, sig, rnd, out);
}

// round 14
// speedup vs baseline: 1.0667x; 1.0081x over previous
#include <cuda_runtime.h>
#include <cuda_bf16.h>
#include <math.h>
#include <stdint.h>

#define NP    16384
#define DIM   24
#define ESIG  65536
#define ERND  32768
#define KK    50          // reference keeps K+1 (self + K nearest)
#define CANDMAX 64
#define D2_SLACK 8.0f     // bf16 threshold (true cutoff 1.0; error bound ~1.2)

#define MT     128        // tile rows
#define NTILES (NP/MT)    // 128
#define CHUNK  8          // tj tiles per scan CTA
#define NCHUNK 1088       // sum over ti of ceil((128-ti)/8)

#define SIG_BLKS   (ESIG/(256*4))        // 64
#define RND_BLKS   (ERND/(256*4))        // 32
#define SCAN_BLKS  (NCHUNK + SIG_BLKS + RND_BLKS)   // 1184
#define FIN_BLKS   (NP/256)              // 64

// ---------------- device state (static zero-init; final kernel resets) ----------------
__device__ double g_acc[3];
__device__ int    g_done;
__device__ float  g_sq[NP];
__device__ float  g_sqh[NP];
__device__ int    g_pid[NP];
__device__ int    g_ccnt[NP];
__device__ int    g_cidx[NP][CANDMAX];
__device__ uint32_t g_P[NP][8];   // dims 0-15, pair layout [w0,w4,w1,w5,w2,w6,w3,w7]
__device__ uint32_t g_Q[NP][4];   // dims 16-23

// ---------------- helpers ----------------
__device__ __forceinline__ long long ldidx(const void* p, long long i, int is64) {
    if (is64) return ((const long long*)p)[i];
    return (long long)((const int*)p)[i];
}
__device__ __forceinline__ int detect64(const void* p, long long lim) {
    const long long* q = (const long long*)p;
    for (int i = 0; i < 32; i++) {
        long long v = q[i];
        if (v < 0 || v >= lim) return 0;
    }
    return 1;
}
template <int BS>
__device__ __forceinline__ void block_accum(double v, double* target) {
    __shared__ double s[BS];
    int t = threadIdx.x;
    s[t] = v;
    __syncthreads();
    for (int o = BS / 2; o > 0; o >>= 1) {
        if (t < o) s[t] += s[t + o];
        __syncthreads();
    }
    if (t == 0 && s[0] != 0.0) atomicAdd(target, s[0]);
}
__device__ __forceinline__ uint32_t smem_u32(const void* p) {
    uint32_t a;
    asm("{ .reg .u64 t; cvta.to.shared.u64 t, %1; cvt.u32.u64 %0, t; }" : "=r"(a) : "l"(p));
    return a;
}
__device__ __forceinline__ void cpa16(uint32_t s, const void* g) {
    asm volatile("cp.async.cg.shared.global [%0], [%1], 16;" :: "r"(s), "l"(g));
}
#define CPA_COMMIT() asm volatile("cp.async.commit_group;" ::: "memory")
#define CPA_WAIT0()  asm volatile("cp.async.wait_group 0;" ::: "memory")

__device__ __forceinline__ void mma16816(float* d, const uint32_t* a, uint32_t b0, uint32_t b1) {
    asm volatile(
        "mma.sync.aligned.m16n8k16.row.col.f32.bf16.bf16.f32 "
        "{%0,%1,%2,%3}, {%4,%5,%6,%7}, {%8,%9}, {%0,%1,%2,%3};"
        : "+f"(d[0]), "+f"(d[1]), "+f"(d[2]), "+f"(d[3])
        : "r"(a[0]), "r"(a[1]), "r"(a[2]), "r"(a[3]), "r"(b0), "r"(b1));
}
__device__ __forceinline__ void mma1688(float* d, uint32_t a0, uint32_t a1, uint32_t b0) {
    asm volatile(
        "mma.sync.aligned.m16n8k8.row.col.f32.bf16.bf16.f32 "
        "{%0,%1,%2,%3}, {%4,%5}, {%6}, {%0,%1,%2,%3};"
        : "+f"(d[0]), "+f"(d[1]), "+f"(d[2]), "+f"(d[3])
        : "r"(a0), "r"(a1), "r"(b0));
}

__device__ __forceinline__ float edge_d2(const float* __restrict__ emb,
                                         long long a, long long b) {
    const float4* pa = (const float4*)(emb + a * DIM);
    const float4* pb = (const float4*)(emb + b * DIM);
    float s = 0.f;
    #pragma unroll
    for (int q = 0; q < DIM / 4; q++) {
        float4 x = pa[q], y = pb[q];
        float d0 = x.x - y.x, d1 = x.y - y.y, d2 = x.z - y.z, d3 = x.w - y.w;
        s = fmaf(d0, d0, s); s = fmaf(d1, d1, s);
        s = fmaf(d2, d2, s); s = fmaf(d3, d3, s);
    }
    return s;
}

__device__ __forceinline__ uint32_t bf2w(float lo, float hi) {
    __nv_bfloat162 p = __floats2bfloat162_rn(lo, hi);
    return *(uint32_t*)&p;
}

// ---------------- prep: 2 threads per point ----------------
__global__ void __launch_bounds__(256) k_prep(const float* __restrict__ emb,
                                              const void* __restrict__ pid) {
    __shared__ int s_is64;
    if (threadIdx.x == 0) s_is64 = detect64(pid, 1LL << 31);
    __syncthreads();
    int t  = threadIdx.x;
    int pt = blockIdx.x * 128 + (t >> 1);
    int h  = t & 1;
    const float4* src = (const float4*)(emb + (long long)pt * DIM);
    float s = 0.f;
    if (h == 0) {
        float4 v[4];
        #pragma unroll
        for (int q = 0; q < 4; q++) v[q] = src[q];
        float f[16];
        #pragma unroll
        for (int q = 0; q < 4; q++) {
            f[4 * q] = v[q].x; f[4 * q + 1] = v[q].y;
            f[4 * q + 2] = v[q].z; f[4 * q + 3] = v[q].w;
        }
        #pragma unroll
        for (int k = 0; k < 16; k++) s = fmaf(f[k], f[k], s);
        uint32_t w[8];
        #pragma unroll
        for (int j = 0; j < 8; j++) w[j] = bf2w(f[2 * j], f[2 * j + 1]);
        uint4* dst = (uint4*)g_P[pt];
        dst[0] = make_uint4(w[0], w[4], w[1], w[5]);
        dst[1] = make_uint4(w[2], w[6], w[3], w[7]);
    } else {
        float4 v0 = src[4], v1 = src[5];
        s = fmaf(v0.x, v0.x, s); s = fmaf(v0.y, v0.y, s);
        s = fmaf(v0.z, v0.z, s); s = fmaf(v0.w, v0.w, s);
        s = fmaf(v1.x, v1.x, s); s = fmaf(v1.y, v1.y, s);
        s = fmaf(v1.z, v1.z, s); s = fmaf(v1.w, v1.w, s);
        *(uint4*)g_Q[pt] = make_uint4(bf2w(v0.x, v0.y), bf2w(v0.z, v0.w),
                                      bf2w(v1.x, v1.y), bf2w(v1.z, v1.w));
    }
    float tot = s + __shfl_xor_sync(0xffffffff, s, 1);
    if (h == 1) {
        g_sq[pt]   = tot;
        g_sqh[pt]  = 0.5f * tot;
        g_pid[pt]  = (int)ldidx(pid, pt, s_is64);
        g_ccnt[pt] = 0;
    }
}

// ---------------- scan launch: chunked triangular scan + overlapped edges ----------------
__global__ void __launch_bounds__(256) k_scan(const float* __restrict__ emb,
                                              const void* __restrict__ sig,
                                              const void* __restrict__ rnd) {
    int bx = blockIdx.x;
    int t  = threadIdx.x;

    if (bx >= NCHUNK) {
        // ---- edges (latency-bound; overlap with tensor-bound scan) ----
        __shared__ int s_is64;
        int eb = bx - NCHUNK;
        if (eb < SIG_BLKS) {
            if (t == 0) s_is64 = detect64(sig, (long long)NP);
            __syncthreads();
            int base = eb * 256 * 4 + t * 4;
            int is64 = s_is64;
            float s = 0.f;
            #pragma unroll
            for (int e = 0; e < 4; e++) {
                long long a = ldidx(sig, base + e, is64);
                long long b = ldidx(sig, (long long)ESIG + base + e, is64);
                s += edge_d2(emb, a, b) + 1e-12f;
            }
            block_accum<256>((double)s, &g_acc[0]);
        } else {
            if (t == 0) s_is64 = detect64(rnd, (long long)NP);
            __syncthreads();
            int base = (eb - SIG_BLKS) * 256 * 4 + t * 4;
            int is64 = s_is64;
            float s = 0.f;
            #pragma unroll
            for (int e = 0; e < 4; e++) {
                long long a = ldidx(rnd, base + e, is64);
                long long b = ldidx(rnd, (long long)ERND + base + e, is64);
                if (g_pid[a] != g_pid[b]) {
                    float dd = sqrtf(edge_d2(emb, a, b) + 1e-12f);
                    if (dd < 1.0f) {
                        float h = 1.0f - dd;
                        s += h * h;
                    }
                }
            }
            block_accum<256>((double)s, &g_acc[2]);
        }
        return;
    }

    // ---- chunked symmetric scan ----
    __shared__ __align__(16) uint32_t sAP[MT * 8];       // 4 KB
    __shared__ __align__(16) uint32_t sAQ[MT * 4];       // 2 KB
    __shared__ __align__(16) uint32_t sBP[2][MT * 8];    // 8 KB
    __shared__ __align__(16) uint32_t sBQ[2][MT * 4];    // 4 KB
    __shared__ __align__(16) float    sbh[2][MT];        // 1 KB

    int c = bx;
    int ti = 0, rem = c;
    while (true) {
        int ch = (NTILES - ti + CHUNK - 1) >> 3;
        if (rem < ch) break;
        rem -= ch; ti++;
    }
    int tj0 = ti + (rem << 3);
    int tjn = NTILES - tj0; if (tjn > CHUNK) tjn = CHUNK;

    int wid  = t >> 5;
    int lane = t & 31;
    int g    = lane >> 2;
    int tig  = lane & 3;

    // stage A + first B tile
    {
        int row = t >> 1, h = t & 1;
        cpa16(smem_u32(&sAP[row * 8 + h * 4]), &g_P[ti * MT + row][h * 4]);
        cpa16(smem_u32(&sBP[0][row * 8 + h * 4]), &g_P[tj0 * MT + row][h * 4]);
        if (t < MT) cpa16(smem_u32(&sAQ[t * 4]), &g_Q[ti * MT + t][0]);
        else cpa16(smem_u32(&sBQ[0][(t - MT) * 4]), &g_Q[tj0 * MT + (t - MT)][0]);
        if (t < MT / 4) cpa16(smem_u32(&sbh[0][t * 4]), &g_sqh[tj0 * MT + t * 4]);
        CPA_COMMIT();
        CPA_WAIT0();
    }
    __syncthreads();

    // A fragments (loaded once per chunk)
    int sbase = wid * 16;
    uint32_t a16[4], a8_0, a8_1;
    {
        int r0 = sbase + g, r1 = sbase + g + 8;
        uint2 p;
        p = *(const uint2*)&sAP[r0 * 8 + 2 * tig]; a16[0] = p.x; a16[2] = p.y;
        p = *(const uint2*)&sAP[r1 * 8 + 2 * tig]; a16[1] = p.x; a16[3] = p.y;
        a8_0 = sAQ[r0 * 4 + tig];
        a8_1 = sAQ[r1 * 4 + tig];
    }
    int rowg0 = ti * MT + sbase + g;
    int rowg1 = rowg0 + 8;
    float thr0 = 0.5f * (g_sq[rowg0] - D2_SLACK);
    float thr1 = 0.5f * (g_sq[rowg1] - D2_SLACK);
    float thrmin = fminf(thr0, thr1);

    for (int jj = 0; jj < tjn; jj++) {
        int tj  = tj0 + jj;
        int buf = jj & 1;

        if (jj + 1 < tjn) {       // prefetch next B tile
            int tn = tj + 1, nb2 = buf ^ 1;
            int row = t >> 1, h = t & 1;
            cpa16(smem_u32(&sBP[nb2][row * 8 + h * 4]), &g_P[tn * MT + row][h * 4]);
            if (t < MT) cpa16(smem_u32(&sBQ[nb2][t * 4]), &g_Q[tn * MT + t][0]);
            if (t < MT / 4) cpa16(smem_u32(&sbh[nb2][t * 4]), &g_sqh[tn * MT + t * 4]);
            CPA_COMMIT();
        }

        bool offdiag = (tj != ti);
        int cbase = tj * MT;
        const uint32_t* BP = sBP[buf];
        const uint32_t* BQ = sBQ[buf];
        const float*    SH = sbh[buf];

        // software-pipelined nb loop: load nb+1 fragments before nb epilogue
        uint2    bp  = *(const uint2*)&BP[g * 8 + 2 * tig];
        uint32_t bq  = BQ[g * 4 + tig];
        float2   sb2 = *(const float2*)&SH[tig * 2];

        #pragma unroll 4
        for (int nb = 0; nb < MT / 8; nb++) {
            float d[4] = {0.f, 0.f, 0.f, 0.f};
            mma16816(d, a16, bp.x, bp.y);
            mma1688(d, a8_0, a8_1, bq);

            int c0 = nb * 8 + tig * 2;
            float2 csb2 = sb2;

            if (nb + 1 < MT / 8) {      // prefetch next fragments during epilogue
                int cbn = (nb + 1) * 8;
                bp  = *(const uint2*)&BP[(cbn + g) * 8 + 2 * tig];
                bq  = BQ[(cbn + g) * 4 + tig];
                sb2 = *(const float2*)&SH[cbn + tig * 2];
            }

            float dmax = fmaxf(fmaxf(d[0], d[1]), fmaxf(d[2], d[3]));
            if (dmax > thrmin + fminf(csb2.x, csb2.y)) {       // rare
                if (d[0] > thr0 + csb2.x) {
                    int jg = cbase + c0;
                    int p = atomicAdd(&g_ccnt[rowg0], 1);
                    if (p < CANDMAX) g_cidx[rowg0][p] = jg;
                    if (offdiag) {
                        int q = atomicAdd(&g_ccnt[jg], 1);
                        if (q < CANDMAX) g_cidx[jg][q] = rowg0;
                    }
                }
                if (d[1] > thr0 + csb2.y) {
                    int jg = cbase + c0 + 1;
                    int p = atomicAdd(&g_ccnt[rowg0], 1);
                    if (p < CANDMAX) g_cidx[rowg0][p] = jg;
                    if (offdiag) {
                        int q = atomicAdd(&g_ccnt[jg], 1);
                        if (q < CANDMAX) g_cidx[jg][q] = rowg0;
                    }
                }
                if (d[2] > thr1 + csb2.x) {
                    int jg = cbase + c0;
                    int p = atomicAdd(&g_ccnt[rowg1], 1);
                    if (p < CANDMAX) g_cidx[rowg1][p] = jg;
                    if (offdiag) {
                        int q = atomicAdd(&g_ccnt[jg], 1);
                        if (q < CANDMAX) g_cidx[jg][q] = rowg1;
                    }
                }
                if (d[3] > thr1 + csb2.y) {
                    int jg = cbase + c0 + 1;
                    int p = atomicAdd(&g_ccnt[rowg1], 1);
                    if (p < CANDMAX) g_cidx[rowg1][p] = jg;
                    if (offdiag) {
                        int q = atomicAdd(&g_ccnt[jg], 1);
                        if (q < CANDMAX) g_cidx[jg][q] = rowg1;
                    }
                }
            }
        }
        CPA_WAIT0();
        __syncthreads();
    }
}

// ---------------- final: finalize rows, then finish+reset ----------------
__global__ void __launch_bounds__(256) k_final(const float* __restrict__ emb, float* out) {
    int t   = threadIdx.x;
    int row = blockIdx.x * 256 + t;
    double local = 0.0;
    int nc = g_ccnt[row];
    if (nc > CANDMAX) nc = CANDMAX;
    if (nc > 1) {      // nc==1 => only self => contributes 0
        float cd2[CANDMAX];
        int   cidx[CANDMAX];
        float sqr = g_sq[row];
        const float4* pr = (const float4*)(emb + (long long)row * DIM);
        float4 r4[DIM / 4];
        #pragma unroll
        for (int q = 0; q < DIM / 4; q++) r4[q] = pr[q];
        for (int qq = 0; qq < nc; qq++) {
            int j = g_cidx[row][qq];
            const float4* pc = (const float4*)(emb + (long long)j * DIM);
            float dot = 0.f;
            #pragma unroll
            for (int q = 0; q < DIM / 4; q++) {
                float4 y = pc[q];
                dot = fmaf(r4[q].x, y.x, dot); dot = fmaf(r4[q].y, y.y, dot);
                dot = fmaf(r4[q].z, y.z, dot); dot = fmaf(r4[q].w, y.w, dot);
            }
            cd2[qq]  = sqr + g_sq[j] - 2.0f * dot;   // exact fp32
            cidx[qq] = j;
        }
        for (int i = 1; i < nc; i++) {               // ascending (d2, idx)
            float dv = cd2[i]; int iv = cidx[i];
            int j = i - 1;
            while (j >= 0 && (cd2[j] > dv || (cd2[j] == dv && cidx[j] > iv))) {
                cd2[j + 1] = cd2[j]; cidx[j + 1] = cidx[j]; j--;
            }
            cd2[j + 1] = dv; cidx[j + 1] = iv;
        }
        int mypid = g_pid[row];
        int lim = nc < (KK + 1) ? nc : (KK + 1);
        for (int q = 0; q < lim; q++) {
            int j = cidx[q];
            if (j != row && g_pid[j] != mypid) {
                float d = sqrtf(fmaxf(cd2[q], 0.0f) + 1e-12f);
                if (d < 1.0f) {
                    float h = 1.0f - d;
                    local += (double)(h * h);
                }
            }
        }
    }
    block_accum<256>(local, &g_acc[1]);

    if (t == 0) {
        __threadfence();
        int done = atomicAdd(&g_done, 1);
        if (done == FIN_BLKS - 1) {
            out[0] = (float)(g_acc[0] / (double)ESIG +
                             g_acc[1] / (double)NP +
                             g_acc[2] / (double)ERND);
            // reset for next graph replay
            g_acc[0] = 0.0; g_acc[1] = 0.0; g_acc[2] = 0.0;
            g_done = 0;
        }
    }
}

// ---------------- launch ----------------
extern "C" void kernel_launch(void* const* d_in, const int* in_sizes, int n_in,
                              void* d_out, int out_size) {
    const float* emb = (const float*)d_in[0];
    const void*  sig = d_in[1];
    const void*  rnd = d_in[2];
    const void*  pid = d_in[3];
    float* out = (float*)d_out;

    k_prep<<<NP * 2 / 256, 256>>>(emb, pid);
    k_scan<<<SCAN_BLKS, 256>>>(emb, sig, rnd);
    k_final<<<FIN_BLKS, 256>>>(emb, out);
}